// round 9
// baseline (speedup 1.0000x reference)
#include <cuda_runtime.h>
#include <stdint.h>

// Problem constants (from reference setup_inputs)
#define BSZ      32
#define XMAX     1024
#define VOCAB    1000
#define YMAX     128
#define LSTATES  257                   // 2*YMAX + 1
#define LOGZERO  (-1e10f)
#define GROW     132                   // gathered row stride (floats): 128 tok + blank + pad
#define RING     16                    // cp.async smem ring depth (rows)
#define ROWB     (GROW * 4)            // row bytes = 528

#define MASK_ELEMS ((size_t)BSZ * (YMAX + 1) * XMAX)   // 32*129*1024

// cross-kernel scratch (static device globals: allocation-guard legal)
__device__ __align__(16) float g_gather[(size_t)BSZ * XMAX * GROW];  // ~17 MB
__device__ __align__(16) short g_csum[BSZ * XMAX];  // exclusive non-blank count per (b,t)
__device__ int   g_ssv[BSZ];           // src_size per batch

// dynamic smem: [0,128KB) bp codes  |  [128KB, +RING*528B) gathered-row ring
extern __shared__ uint32_t dyn_sm[];

__device__ __forceinline__ uint32_t smem_u32(const void* p) {
    uint32_t a;
    asm("{ .reg .u64 t; cvta.to.shared.u64 t, %1; cvt.u32.u64 %0, t; }"
        : "=r"(a) : "l"(p));
    return a;
}
__device__ __forceinline__ void cp_async16(uint32_t dst, const void* src) {
    asm volatile("cp.async.cg.shared.global [%0], [%1], 16;" :: "r"(dst), "l"(src));
}
#define CP_COMMIT() asm volatile("cp.async.commit_group;" ::: "memory")
#define CP_WAIT14() asm volatile("cp.async.wait_group 14;" ::: "memory")

// ---------------- Stage 1: time-invariant column gather ----------------
// g_gather[b][t][j] = ctc[b][t][ys[b][j]] for j<128 ; [128] = ctc[b][t][blank]
__global__ __launch_bounds__(256)
void fanat_gather(const float* __restrict__ ctc,
                  const int*   __restrict__ ys,
                  const int*   __restrict__ blank_p)
{
    const int idx = blockIdx.x * 256 + threadIdx.x;
    const int total = BSZ * XMAX * GROW;
    if (idx >= total) return;
    const int j  = idx % GROW;
    if (j > 128) return;
    const int bt = idx / GROW;              // b*XMAX + t
    const int b  = bt >> 10;                // XMAX = 1024

    const int blank = blank_p ? blank_p[0] : 0;
    const int tok = (j < 128) ? ys[b * YMAX + j] : blank;
    g_gather[(size_t)bt * GROW + j] = ctc[(size_t)bt * VOCAB + tok];
}

// ---------------- Stage 2: single-warp-per-batch Viterbi ----------------
__global__ __launch_bounds__(32, 1)
void fanat_forward(const int*   __restrict__ src_size,  // [BSZ]
                   const int*   __restrict__ ys,        // [BSZ, YMAX]
                   const int*   __restrict__ ylens,     // [BSZ]
                   const int*   __restrict__ blank_p,   // [1] or nullptr
                   float*       __restrict__ out)
{
    __shared__ float alphaAt[LSTATES + 3];
    __shared__ short states_sh[XMAX];
    __shared__ int   start_sh;

    uint32_t* bp_sm = dyn_sm;                                  // [XMAX][32] u32
    char*     ring  = (char*)(dyn_sm + XMAX * 32);             // RING rows of 528B
    const uint32_t ring_s = smem_u32(ring);

    const int b    = blockIdx.x;
    const int lane = threadIdx.x;

    const int blank = blank_p ? blank_p[0] : 0;
    const int ss = src_size[b];
    const int yl = ylens[b];
    const int pl = 2 * yl + 1;

    // Lane owns states s = 8*lane + k, k=0..8 (k=8 duplicates lane+1's k=0;
    // redundant compute keeps lanes uniform -> 1 shfl/step, no barriers).
    int tokO[4];
#pragma unroll
    for (int j = 0; j < 4; j++) tokO[j] = ys[b * YMAX + 4 * lane + j];

    const int prevLab = (lane > 0) ? ys[b * YMAX + 4 * lane - 1] : -1;
    bool sameO[4];
    sameO[0] = (lane == 0) ? true : (tokO[0] == prevLab);  // s-2 < 0 for lane0
    sameO[1] = (tokO[1] == tokO[0]);
    sameO[2] = (tokO[2] == tokO[1]);
    sameO[3] = (tokO[3] == tokO[2]);

    bool outF[9];
#pragma unroll
    for (int k = 0; k < 9; k++) outF[k] = (8 * lane + k) >= pl;

    const float* grow_base = g_gather + (size_t)b * XMAX * GROW;

    // issue async copy of one gathered row into ring slot (row clamped)
    auto issue_row = [&](int row) {
        int rp = row; if (rp > XMAX - 1) rp = XMAX - 1;
        const char* src = (const char*)(grow_base + (size_t)rp * GROW);
        const uint32_t dst = ring_s + (row & (RING - 1)) * ROWB;
        cp_async16(dst + lane * 16, src + lane * 16);
        if (lane == 0) cp_async16(dst + 512, src + 512);   // floats 128..131 (blank)
        CP_COMMIT();
    };

    float a[9];
#pragma unroll
    for (int k = 0; k < 9; k++) a[k] = LOGZERO;
    if (lane == 0) a[0] = 0.0f;

    // one Viterbi step. h1 = alpha_t[8l-1] (prefetched via previous shfl);
    // computes na[7] FIRST and launches the next halo shfl immediately so its
    // 26-cyc latency overlaps the remaining 8 states' compute.
    auto step = [&](int t, float lb, float l1, float l3, float l5, float l7,
                    float h1, float& h1n_raw) {
        const float lpk[9] = {lb, l1, lb, l3, lb, l5, lb, l7, lb};
        float na[9];
        uint32_t av[9];

        // ---- k = 7 first (feeds next step's halo) ----
        {
            const float m0 = a[7], m1 = a[6];
            const float m2 = sameO[3] ? LOGZERO : a[5];
            float best = fmaxf(m0, m1);
            int   arg  = (m1 > m0) ? 1 : 0;
            if (m2 > best) { best = m2; arg = 2; }
            na[7] = (outF[7] ? LOGZERO : best) + lpk[7];
            av[7] = (uint32_t)arg << 14;
        }
        h1n_raw = __shfl_up_sync(0xffffffffu, na[7], 1);   // in flight during rest

        // ---- remaining states ----
#pragma unroll
        for (int k = 0; k < 9; k++) {
            if (k == 7) continue;
            const float m0 = a[k];
            const float m1 = (k == 0) ? h1 : a[k - 1];
            float m2;
            if (k & 1) {
                const float mm = (k == 1) ? h1 : a[k - 2];   // alpha[s-2]
                m2 = sameO[k >> 1] ? LOGZERO : mm;
            } else {
                m2 = LOGZERO;                                // even: always "same"
            }
            float best = fmaxf(m0, m1);
            int   arg  = (m1 > m0) ? 1 : 0;      // first-max tie-break (jnp.argmax)
            if (m2 > best) { best = m2; arg = 2; }
            na[k] = (outF[k] ? LOGZERO : best) + lpk[k];
            av[k] = (uint32_t)arg << (2 * k);
        }
        // balanced OR tree (avoid 9-deep serial chain)
        const uint32_t w01 = av[0] | av[1], w23 = av[2] | av[3];
        const uint32_t w45 = av[4] | av[5], w67 = av[6] | av[7];
        const uint32_t w = (w01 | w23) | (w45 | w67) | av[8];
        bp_sm[t * 32 + lane] = w;
#pragma unroll
        for (int k = 0; k < 9; k++) a[k] = na[k];
    };

    // ---- pipeline prologue: fill the ring, load row 0 into regs ----
#pragma unroll
    for (int r = 0; r < RING; r++) issue_row(r);
    CP_WAIT14();                                  // rows 0..1 resident
    const float4* ring4 = (const float4*)ring;
    const float*  ringf = (const float*)ring;
    float4 cv = ring4[lane];                      // slot 0, lane chunk
    float  cb = ringf[128];                       // slot 0, blank

    float h1 = __shfl_up_sync(0xffffffffu, a[7], 1);   // alpha_0[8l-1]
    if (lane == 0) h1 = LOGZERO;

    // ---- forward Viterbi, t in [0, ss) ----
    for (int t = 0; t < ss; ++t) {
        float h1n;
        step(t, cb, cv.x, cv.y, cv.z, cv.w, h1, h1n);
        h1 = (lane == 0) ? LOGZERO : h1n;
        issue_row(t + RING);
        CP_WAIT14();                              // rows <= t+2 resident
        const int slot = (t + 1) & (RING - 1);
        cv = ring4[slot * (ROWB / 16) + lane];
        cb = ringf[slot * GROW + 128];
    }

    // ---------------- score / start state (alpha at t = ss is in regs) ----------------
#pragma unroll
    for (int k = 0; k < 9; k++) {
        const int s = 8 * lane + k;
        if (s < LSTATES) alphaAt[s] = a[k];
    }
    __syncwarp();
    if (lane == 0) {
        const float s1 = alphaAt[pl - 1];
        const float s2 = alphaAt[pl - 2];
        start_sh = (s1 > s2) ? (pl - 1) : (pl - 2);
        out[b] = fmaxf(s1, s2);                              // score
        out[32 + MASK_ELEMS + b] = (float)(yl + 1);          // ylens + 1
    }
    __syncwarp();

    // ---------------- backtrace (lane 0, LDS chase) ----------------
    for (int t = ss + lane; t < XMAX; t += 32) states_sh[t] = 0;
    if (lane == 0) {
        int carry = start_sh;
        states_sh[ss - 1] = (short)carry;
        for (int t = ss - 2; t >= 0; --t) {
            int lidx = carry >> 3; if (lidx > 31) lidx = 31;   // state 256 -> lane31,k=8
            const uint32_t word = bp_sm[(t + 1) * 32 + lidx];
            const int kk = carry - (lidx << 3);
            carry -= (int)((word >> (2 * kk)) & 3u);
            states_sh[t] = (short)carry;
        }
    }
    __syncwarp();

    // ---------------- collapse repeats + exclusive non-blank count ----------------
    const int base_t = lane * 32;
    int prevTok = 0;
    if (base_t > 0) {
        const int sp = states_sh[base_t - 1];
        prevTok = (sp & 1) ? ys[b * YMAX + ((sp - 1) >> 1)] : blank;
    }
    int lane_sum = 0;
    {
        int pt = prevTok;
        for (int i = 0; i < 32; i++) {
            const int st = states_sh[base_t + i];
            const int tk = (st & 1) ? ys[b * YMAX + ((st - 1) >> 1)] : blank;
            const int col = (tk == pt) ? 0 : tk;
            lane_sum += (col != blank) ? 1 : 0;
            pt = tk;
        }
    }
    int offs = lane_sum;
#pragma unroll
    for (int d = 1; d < 32; d <<= 1) {
        const int v = __shfl_up_sync(0xffffffffu, offs, d);
        if (lane >= d) offs += v;
    }
    offs -= lane_sum;
    {
        int pt = prevTok, run = offs;
        for (int i = 0; i < 32; i++) {
            const int t = base_t + i;
            g_csum[b * XMAX + t] = (short)run;               // exclusive count at t
            const int st = states_sh[t];
            const int tk = (st & 1) ? ys[b * YMAX + ((st - 1) >> 1)] : blank;
            const int col = (tk == pt) ? 0 : tk;
            run += (col != blank) ? 1 : 0;
            pt = tk;
        }
    }
    if (lane == 0) g_ssv[b] = ss;
}

// ---------------- Stage 3: trigger_mask streaming store ----------------
// grid: (per_b/4/256 = 129, BSZ) -> no 64-bit div/mod in the hot path
__global__ __launch_bounds__(256)
void fanat_mask(float* __restrict__ out)
{
    const int bb   = blockIdx.y;
    const int idx4 = blockIdx.x * 256 + threadIdx.x;        // [0, 33024)
    const int rem  = idx4 * 4;                              // [0, 132096)
    const int j    = rem >> 10;                             // XMAX = 1024
    const int t0   = rem & (XMAX - 1);

    const int ss = g_ssv[bb];
    const short4 cs = *(const short4*)(g_csum + bb * XMAX + t0);
    const int cv[4] = {cs.x, cs.y, cs.z, cs.w};

    float4 v;
    float* vv = &v.x;
#pragma unroll
    for (int u = 0; u < 4; u++) {
        const int t = t0 + u;
        const bool in = (t < ss);
        const int c = cv[u];
        bool r;
        if (j < YMAX) r = in && (c == j);
        else          r = in && (c == YMAX || t == ss - 1);
        vv[u] = r ? 1.0f : 0.0f;
    }
    const size_t e = (size_t)bb * ((YMAX + 1) * XMAX) + rem;
    *(float4*)(out + 32 + e) = v;
}

extern "C" void kernel_launch(void* const* d_in, const int* in_sizes, int n_in,
                              void* d_out, int out_size)
{
    // metadata order: ctc_out(f32), src_mask(bool, unused), src_size(i32),
    //                 ys(i32), ylens(i32), blank(i32 scalar)
    const float* ctc      = (const float*)d_in[0];
    const int*   src_size = (const int*)d_in[2];
    const int*   ys       = (const int*)d_in[3];
    const int*   ylens    = (const int*)d_in[4];
    const int*   blank_p  = (n_in > 5) ? (const int*)d_in[5] : nullptr;

    {   // Stage 1: gather
        const int total = BSZ * XMAX * GROW;
        fanat_gather<<<(total + 255) / 256, 256>>>(ctc, ys, blank_p);
    }

    {   // Stage 2: forward Viterbi + backtrace + csum
        const int smem = XMAX * 32 * (int)sizeof(uint32_t) + RING * ROWB;  // 128K + 8.25K
        cudaFuncSetAttribute(fanat_forward,
                             cudaFuncAttributeMaxDynamicSharedMemorySize, smem);
        fanat_forward<<<BSZ, 32, smem>>>(src_size, ys, ylens, blank_p, (float*)d_out);
    }

    {   // Stage 3: trigger_mask
        dim3 grid((YMAX + 1) * XMAX / 4 / 256, BSZ);        // (129, 32)
        fanat_mask<<<grid, 256>>>((float*)d_out);
    }
}

// round 10
// speedup vs baseline: 1.1185x; 1.1185x over previous
#include <cuda_runtime.h>
#include <stdint.h>

// Problem constants (from reference setup_inputs)
#define BSZ      32
#define XMAX     1024
#define VOCAB    1000
#define YMAX     128
#define LSTATES  257                   // 2*YMAX + 1
#define LOGZERO  (-1e10f)
#define ROWF     260                   // gathered row floats: 257 states + 3 pad
#define ROWB     (ROWF * 4)            // 1040 bytes
#define SLICEB   512                   // per-warp slice bytes (128 states)
#define RING     8                     // cp.async ring depth (rows)
#define REF      32                    // refresh period (steps)
#define NTH      128                   // 4 warps

#define MASK_ELEMS ((size_t)BSZ * (YMAX + 1) * XMAX)   // 32*129*1024

// cross-kernel scratch (static device globals: allocation-guard legal)
__device__ __align__(16) float g_gather[(size_t)BSZ * XMAX * ROWF];  // ~34 MB
__device__ __align__(16) short g_csum[BSZ * XMAX];
__device__ int   g_ssv[BSZ];

// dynamic smem: [0,128KB) bp bytes | [128KB, +4*RING*512) per-warp rings
extern __shared__ uint8_t dyn_sm[];

__device__ __forceinline__ uint32_t smem_u32(const void* p) {
    uint32_t a;
    asm("{ .reg .u64 t; cvta.to.shared.u64 t, %1; cvt.u32.u64 %0, t; }"
        : "=r"(a) : "l"(p));
    return a;
}
__device__ __forceinline__ void cp_async16(uint32_t dst, const void* src) {
    asm volatile("cp.async.cg.shared.global [%0], [%1], 16;" :: "r"(dst), "l"(src));
}
#define CP_COMMIT() asm volatile("cp.async.commit_group;" ::: "memory")
#define CP_WAIT6()  asm volatile("cp.async.wait_group 6;" ::: "memory")

// ---------------- Stage 1: per-state gather ----------------
// g_gather[b][t][s] = ctc[b][t][path[s]]; s odd -> ys[(s-1)/2], even -> blank
__global__ __launch_bounds__(256)
void fanat_gather(const float* __restrict__ ctc,
                  const int*   __restrict__ ys,
                  const int*   __restrict__ blank_p)
{
    const int idx = blockIdx.x * 256 + threadIdx.x;
    const int total = BSZ * XMAX * ROWF;
    if (idx >= total) return;
    const int j  = idx % ROWF;
    const int bt = idx / ROWF;              // b*XMAX + t
    const int b  = bt >> 10;                // XMAX = 1024

    float val = LOGZERO;
    if (j < LSTATES) {
        const int blank = blank_p ? blank_p[0] : 0;
        const int tok = (j & 1) ? ys[b * YMAX + (j >> 1)] : blank;
        val = ctc[(size_t)bt * VOCAB + tok];
    }
    g_gather[(size_t)bt * ROWF + j] = val;
}

// ---------------- Stage 2: 4-warp-per-batch Viterbi ----------------
__global__ __launch_bounds__(NTH, 1)
void fanat_forward(const int*   __restrict__ src_size,
                   const int*   __restrict__ ys,
                   const int*   __restrict__ ylens,
                   const int*   __restrict__ blank_p,
                   float*       __restrict__ out)
{
    __shared__ float alphaAt[LSTATES];
    __shared__ short states_sh[XMAX];
    __shared__ __align__(16) float pub[4 * 64];
    __shared__ int   wsum[4];
    __shared__ int   start_sh;

    uint8_t* bp_sm = dyn_sm;                                   // [XMAX][128] bytes
    uint8_t* rings = dyn_sm + XMAX * NTH;                      // 4 * RING * 512

    const int b    = blockIdx.x;
    const int tid  = threadIdx.x;
    const int w    = tid >> 5;
    const int lane = tid & 31;

    const int blank = blank_p ? blank_p[0] : 0;
    const int ss = src_size[b];
    const int yl = ylens[b];
    const int pl = 2 * yl + 1;

    const int bw = 64 * w;
    const int s0 = bw + 4 * lane;          // first state this lane computes

    // time-invariant per-state flags (k=0..3; parity of s0+k == parity of k)
    bool oF0 = (s0 + 0) >= pl, oF1 = (s0 + 1) >= pl;
    bool oF2 = (s0 + 2) >= pl, oF3 = (s0 + 3) >= pl;
    // same_tr for odd states: path[s] == path[s-2]
    bool same1, same3;
    {
        const int s1 = s0 + 1, s3 = s0 + 3;
        same1 = (s1 == 1) ? true
              : (ys[b * YMAX + ((s1 - 1) >> 1)] == ys[b * YMAX + ((s1 - 3) >> 1)]);
        same3 = (ys[b * YMAX + ((s3 - 1) >> 1)] == ys[b * YMAX + ((s3 - 3) >> 1)]);
    }

    // ring: each lane copies/reads ONLY its own 16B chunk (no cross-thread dep)
    const char* row0 = (const char*)(g_gather + (size_t)b * XMAX * ROWF);
    int src_off = bw * 4 + lane * 16;
    if (src_off > ROWB - 16) src_off = ROWB - 16;      // clamp (warp3 top lanes)
    const uint32_t ring_s = smem_u32(rings + w * RING * SLICEB);
    const uint32_t my_dst = ring_s + lane * 16;
    const char*    my_ring = (const char*)(rings + w * RING * SLICEB) + lane * 16;

    auto issue_row = [&](int row) {
        int rp = row; if (rp > XMAX - 1) rp = XMAX - 1;
        cp_async16(my_dst + (row & (RING - 1)) * SLICEB, row0 + (size_t)rp * ROWB + src_off);
        CP_COMMIT();
    };

    float a0 = LOGZERO, a1 = LOGZERO, a2 = LOGZERO, a3 = LOGZERO;
    if (w == 0 && lane == 0) a0 = 0.0f;    // alpha0[0] = 0

    const int bp_addr0 = (lane << 2) + w;  // + t*128

    // prologue: fill ring
#pragma unroll
    for (int r = 0; r < RING; r++) issue_row(r);
    CP_WAIT6();

    // ---- forward Viterbi with periodic refresh ----
    for (int t0 = 0; t0 < ss; t0 += REF) {
        const int tend = (t0 + REF < ss) ? (t0 + REF) : ss;
#pragma unroll 4
        for (int t = t0; t < tend; ++t) {
            const float4 lp = *(const float4*)(my_ring + (t & (RING - 1)) * SLICEB);
            float h1 = __shfl_up_sync(0xffffffffu, a3, 1);     // alpha[s0-1]
            if (lane == 0) h1 = LOGZERO;

            // k=0 (even: no m2)
            float b0 = fmaxf(a0, h1);  int g0 = (h1 > a0) ? 1 : 0;
            float n0 = (oF0 ? LOGZERO : b0) + lp.x;
            // k=1 (odd: m2 = alpha[s0-1] unless same)
            float b1 = fmaxf(a1, a0);  int g1 = (a0 > a1) ? 1 : 0;
            float m2a = same1 ? LOGZERO : h1;
            if (m2a > b1) { b1 = m2a; g1 = 2; }
            float n1 = (oF1 ? LOGZERO : b1) + lp.y;
            // k=2 (even)
            float b2 = fmaxf(a2, a1);  int g2 = (a1 > a2) ? 1 : 0;
            float n2 = (oF2 ? LOGZERO : b2) + lp.z;
            // k=3 (odd: m2 = a1 unless same)
            float b3 = fmaxf(a3, a2);  int g3 = (a2 > a3) ? 1 : 0;
            float m2b = same3 ? LOGZERO : a1;
            if (m2b > b3) { b3 = m2b; g3 = 2; }
            float n3 = (oF3 ? LOGZERO : b3) + lp.w;

            bp_sm[t * NTH + bp_addr0] =
                (uint8_t)(g0 | (g1 << 2) | (g2 << 4) | (g3 << 6));
            a0 = n0; a1 = n1; a2 = n2; a3 = n3;

            issue_row(t + RING);
            CP_WAIT6();
        }
        if (tend < ss) {
            // publish upper half (lanes 16..31 -> warp w+1's refresh zone)
            if (lane >= 16) {
                float4 v = make_float4(a0, a1, a2, a3);
                *(float4*)&pub[w * 64 + (lane - 16) * 4] = v;
            }
            __syncthreads();
            if (w > 0 && lane < 16) {      // refresh lower half from warp w-1
                float4 v = *(const float4*)&pub[(w - 1) * 64 + lane * 4];
                a0 = v.x; a1 = v.y; a2 = v.z; a3 = v.w;
            }
            __syncthreads();
        }
    }

    // ---- publish owned alpha at t = ss ----
    {
        const int olo = (w == 0) ? 0   : bw + 64;
        const int ohi = (w == 3) ? 257 : bw + 128;
        if (s0 + 0 >= olo && s0 + 0 < ohi) alphaAt[s0 + 0] = a0;
        if (s0 + 1 >= olo && s0 + 1 < ohi) alphaAt[s0 + 1] = a1;
        if (s0 + 2 >= olo && s0 + 2 < ohi) alphaAt[s0 + 2] = a2;
        if (s0 + 3 >= olo && s0 + 3 < ohi) alphaAt[s0 + 3] = a3;
    }
    for (int t = ss + tid; t < XMAX; t += NTH) states_sh[t] = 0;
    __syncthreads();

    if (tid == 0) {
        const float v1 = alphaAt[pl - 1];
        const float v2 = alphaAt[pl - 2];
        start_sh = (v1 > v2) ? (pl - 1) : (pl - 2);
        out[b] = fmaxf(v1, v2);                              // score
        out[32 + MASK_ELEMS + b] = (float)(yl + 1);          // ylens + 1
    }
    __syncthreads();

    // ---- backtrace (tid 0, LDS chase through bp bytes) ----
    if (tid == 0) {
        int carry = start_sh;
        states_sh[ss - 1] = (short)carry;
        for (int t = ss - 2; t >= 0; --t) {
            const int s  = carry;
            const int wi = (s >= 128) + (s >= 192) + (s >= 256);
            const int local = s - (wi << 6);
            const uint8_t byte = bp_sm[(t + 1) * NTH + (local & ~3) + wi];
            const int kk = local & 3;
            carry = s - (int)((byte >> (2 * kk)) & 3u);
            states_sh[t] = (short)carry;
        }
    }
    __syncthreads();

    // ---- collapse repeats + exclusive non-blank count (8 t's per thread) ----
    const int t_base = tid * 8;
    int prevTok = 0;
    if (t_base > 0) {
        const int sp = states_sh[t_base - 1];
        prevTok = (sp & 1) ? ys[b * YMAX + ((sp - 1) >> 1)] : blank;
    }
    int lsum = 0;
    {
        int pt = prevTok;
#pragma unroll
        for (int i = 0; i < 8; i++) {
            const int st = states_sh[t_base + i];
            const int tk = (st & 1) ? ys[b * YMAX + ((st - 1) >> 1)] : blank;
            const int col = (tk == pt) ? 0 : tk;
            lsum += (col != blank) ? 1 : 0;
            pt = tk;
        }
    }
    int offs = lsum;
#pragma unroll
    for (int d = 1; d < 32; d <<= 1) {
        const int v = __shfl_up_sync(0xffffffffu, offs, d);
        if (lane >= d) offs += v;
    }
    if (lane == 31) wsum[w] = offs;       // warp total
    offs -= lsum;                          // exclusive within warp
    __syncthreads();
    for (int ww = 0; ww < w; ++ww) offs += wsum[ww];
    {
        int pt = prevTok, run = offs;
#pragma unroll
        for (int i = 0; i < 8; i++) {
            const int t = t_base + i;
            g_csum[b * XMAX + t] = (short)run;
            const int st = states_sh[t];
            const int tk = (st & 1) ? ys[b * YMAX + ((st - 1) >> 1)] : blank;
            const int col = (tk == pt) ? 0 : tk;
            run += (col != blank) ? 1 : 0;
            pt = tk;
        }
    }
    if (tid == 0) g_ssv[b] = ss;
}

// ---------------- Stage 3: trigger_mask streaming store ----------------
__global__ __launch_bounds__(256)
void fanat_mask(float* __restrict__ out)
{
    const int bb   = blockIdx.y;
    const int idx4 = blockIdx.x * 256 + threadIdx.x;        // [0, 33024)
    const int rem  = idx4 * 4;                              // [0, 132096)
    const int j    = rem >> 10;                             // XMAX = 1024
    const int t0   = rem & (XMAX - 1);

    const int ss = g_ssv[bb];
    const short4 cs = *(const short4*)(g_csum + bb * XMAX + t0);
    const int cv[4] = {cs.x, cs.y, cs.z, cs.w};

    float4 v;
    float* vv = &v.x;
#pragma unroll
    for (int u = 0; u < 4; u++) {
        const int t = t0 + u;
        const bool in = (t < ss);
        const int c = cv[u];
        bool r;
        if (j < YMAX) r = in && (c == j);
        else          r = in && (c == YMAX || t == ss - 1);
        vv[u] = r ? 1.0f : 0.0f;
    }
    const size_t e = (size_t)bb * ((YMAX + 1) * XMAX) + rem;
    *(float4*)(out + 32 + e) = v;
}

extern "C" void kernel_launch(void* const* d_in, const int* in_sizes, int n_in,
                              void* d_out, int out_size)
{
    // metadata order: ctc_out(f32), src_mask(bool, unused), src_size(i32),
    //                 ys(i32), ylens(i32), blank(i32 scalar)
    const float* ctc      = (const float*)d_in[0];
    const int*   src_size = (const int*)d_in[2];
    const int*   ys       = (const int*)d_in[3];
    const int*   ylens    = (const int*)d_in[4];
    const int*   blank_p  = (n_in > 5) ? (const int*)d_in[5] : nullptr;

    {   // Stage 1: gather (per-state layout)
        const int total = BSZ * XMAX * ROWF;
        fanat_gather<<<(total + 255) / 256, 256>>>(ctc, ys, blank_p);
    }

    {   // Stage 2: forward Viterbi + backtrace + csum
        const int smem = XMAX * NTH + 4 * RING * SLICEB;    // 128K + 16K
        cudaFuncSetAttribute(fanat_forward,
                             cudaFuncAttributeMaxDynamicSharedMemorySize, smem);
        fanat_forward<<<BSZ, NTH, smem>>>(src_size, ys, ylens, blank_p, (float*)d_out);
    }

    {   // Stage 3: trigger_mask
        dim3 grid((YMAX + 1) * XMAX / 4 / 256, BSZ);        // (129, 32)
        fanat_mask<<<grid, 256>>>((float*)d_out);
    }
}

// round 12
// speedup vs baseline: 1.3441x; 1.2018x over previous
#include <cuda_runtime.h>
#include <stdint.h>

// Problem constants (from reference setup_inputs)
#define BSZ      32
#define XMAX     1024
#define VOCAB    1000
#define YMAX     128
#define LSTATES  257                   // 2*YMAX + 1
#define LOGZERO  (-1e10f)
#define GROW     132                   // compact gathered row floats: 128 tok + blank + pad
#define ROWB     (GROW * 4)            // 528 bytes
#define SLICEB   272                   // per-warp ring slot: 32*8B + 4B blank, padded
#define RING     16                    // ring depth (rows), 4 groups of 4
#define REF      32                    // refresh period (steps)
#define NTH      128                   // 4 warps

#define MASK_ELEMS ((size_t)BSZ * (YMAX + 1) * XMAX)   // 32*129*1024

// cross-kernel scratch (static device globals: allocation-guard legal)
__device__ __align__(16) float g_gather[(size_t)BSZ * XMAX * GROW];  // ~17 MB
__device__ __align__(16) short g_csum[BSZ * XMAX];
__device__ int   g_ssv[BSZ];

// dynamic smem: [0,128KB) bp bytes | [128KB, +4*RING*SLICEB) per-warp rings
extern __shared__ uint8_t dyn_sm[];

__device__ __forceinline__ uint32_t smem_u32(const void* p) {
    uint32_t a;
    asm("{ .reg .u64 t; cvta.to.shared.u64 t, %1; cvt.u32.u64 %0, t; }"
        : "=r"(a) : "l"(p));
    return a;
}
__device__ __forceinline__ void cp_async8(uint32_t dst, const void* src) {
    asm volatile("cp.async.ca.shared.global [%0], [%1], 8;" :: "r"(dst), "l"(src));
}
__device__ __forceinline__ void cp_async4(uint32_t dst, const void* src) {
    asm volatile("cp.async.ca.shared.global [%0], [%1], 4;" :: "r"(dst), "l"(src));
}
#define CP_COMMIT() asm volatile("cp.async.commit_group;" ::: "memory")
#define CP_WAIT3()  asm volatile("cp.async.wait_group 3;" ::: "memory")

// ---------------- Stage 1: compact time-invariant gather ----------------
// g_gather[b][t][j] = ctc[b][t][ys[b][j]] for j<128 ; [128] = ctc[b][t][blank]
__global__ __launch_bounds__(256)
void fanat_gather(const float* __restrict__ ctc,
                  const int*   __restrict__ ys,
                  const int*   __restrict__ blank_p)
{
    const int idx = blockIdx.x * 256 + threadIdx.x;
    const int total = BSZ * XMAX * GROW;
    if (idx >= total) return;
    const int j  = idx % GROW;
    if (j > 128) return;
    const int bt = idx / GROW;              // b*XMAX + t
    const int b  = bt >> 10;                // XMAX = 1024

    const int blank = blank_p ? blank_p[0] : 0;
    const int tok = (j < 128) ? ys[b * YMAX + j] : blank;
    g_gather[(size_t)bt * GROW + j] = ctc[(size_t)bt * VOCAB + tok];
}

// ---------------- Stage 2: 4-warp-per-batch Viterbi ----------------
__global__ __launch_bounds__(NTH, 1)
void fanat_forward(const int*   __restrict__ src_size,
                   const int*   __restrict__ ys,
                   const int*   __restrict__ ylens,
                   const int*   __restrict__ blank_p,
                   float*       __restrict__ out)
{
    __shared__ float alphaAt[LSTATES];
    __shared__ short states_sh[XMAX];
    __shared__ __align__(16) float pub[4 * 64];
    __shared__ int   wsum[4];
    __shared__ int   start_sh;

    uint8_t* bp_sm = dyn_sm;                                   // [XMAX][128] bytes
    uint8_t* rings = dyn_sm + XMAX * NTH;                      // 4 * RING * SLICEB

    const int b    = blockIdx.x;
    const int tid  = threadIdx.x;
    const int w    = tid >> 5;
    const int lane = tid & 31;

    const int blank = blank_p ? blank_p[0] : 0;
    const int ss = src_size[b];
    const int yl = ylens[b];
    const int pl = 2 * yl + 1;

    const int bw = 64 * w;
    const int s0 = bw + 4 * lane;          // first state this lane computes

    bool oF0 = (s0 + 0) >= pl, oF1 = (s0 + 1) >= pl;
    bool oF2 = (s0 + 2) >= pl, oF3 = (s0 + 3) >= pl;

    // token index for odd states s0+1 / s0+3: 32w+2l / +1 (clamped for pad lanes)
    const int i1 = 32 * w + 2 * lane;
    const int i1c = (i1 < 127) ? i1 : 127;
    const int i3c = (i1 + 1 < 127) ? (i1 + 1) : 127;
    bool same1, same3;
    {
        const int p1 = (i1c > 0) ? (i1c - 1) : 0;
        const int p3 = (i3c > 0) ? (i3c - 1) : 0;
        same1 = (s0 + 1 == 1) ? true
              : (ys[b * YMAX + i1c] == ys[b * YMAX + p1]);
        same3 = (ys[b * YMAX + i3c] == ys[b * YMAX + p3]);
    }

    // ring: lane copies/reads only its own 8B chunk + lane0 copies blank
    const char* row0 = (const char*)(g_gather + (size_t)b * XMAX * GROW);
    const int src_off = ((i1 < 126) ? i1 : 126) * 4;    // 8B-aligned, clamped
    uint8_t* warp_ring = rings + w * RING * SLICEB;
    const uint32_t ring_s = smem_u32(warp_ring);
    const uint32_t my_dst = ring_s + lane * 8;

    auto issue_row = [&](int row) {
        int rp = row; if (rp > XMAX - 1) rp = XMAX - 1;
        const char* src = row0 + (size_t)rp * ROWB;
        const uint32_t dst = ring_s + (row & (RING - 1)) * SLICEB;
        cp_async8(my_dst + (row & (RING - 1)) * SLICEB, src + src_off);
        if (lane == 0) cp_async4(dst + 256, src + 512);  // blank (float 128)
    };

    float a0 = LOGZERO, a1 = LOGZERO, a2 = LOGZERO, a3 = LOGZERO;
    if (w == 0 && lane == 0) a0 = 0.0f;    // alpha0[0] = 0

    const int bp_addr0 = (lane << 2) + w;  // + t*128

    auto step = [&](int t) {
        const int slot = t & (RING - 1);
        const float2 tp = *(const float2*)(warp_ring + slot * SLICEB + lane * 8);
        const float  lb = *(const float*)(warp_ring + slot * SLICEB + 256);
        float h1 = __shfl_up_sync(0xffffffffu, a3, 1);     // alpha[s0-1]
        if (lane == 0) h1 = LOGZERO;

        // k=0 (even: no m2)
        float b0 = fmaxf(a0, h1);  int g0 = (h1 > a0) ? 1 : 0;
        float n0 = (oF0 ? LOGZERO : b0) + lb;
        // k=1 (odd: m2 = alpha[s0-1] unless same)
        float b1 = fmaxf(a1, a0);  int g1 = (a0 > a1) ? 1 : 0;
        float m2a = same1 ? LOGZERO : h1;
        if (m2a > b1) { b1 = m2a; g1 = 2; }
        float n1 = (oF1 ? LOGZERO : b1) + tp.x;
        // k=2 (even)
        float b2 = fmaxf(a2, a1);  int g2 = (a1 > a2) ? 1 : 0;
        float n2 = (oF2 ? LOGZERO : b2) + lb;
        // k=3 (odd: m2 = a1 unless same)
        float b3 = fmaxf(a3, a2);  int g3 = (a2 > a3) ? 1 : 0;
        float m2b = same3 ? LOGZERO : a1;
        if (m2b > b3) { b3 = m2b; g3 = 2; }
        float n3 = (oF3 ? LOGZERO : b3) + tp.y;

        bp_sm[t * NTH + bp_addr0] =
            (uint8_t)(g0 | (g1 << 2) | (g2 << 4) | (g3 << 6));
        a0 = n0; a1 = n1; a2 = n2; a3 = n3;
    };

    // prologue: 4 groups of 4 rows
#pragma unroll
    for (int g = 0; g < 4; ++g) {
#pragma unroll
        for (int i = 0; i < 4; ++i) issue_row(4 * g + i);
        CP_COMMIT();
    }

    // ---- forward Viterbi with periodic refresh ----
    for (int t0 = 0; t0 < ss; t0 += REF) {
        const int tend = (t0 + REF < ss) ? (t0 + REF) : ss;
        for (int tb = t0; tb < tend; tb += 4) {
            CP_WAIT3();                        // group tb/4 complete
            const int te = (tb + 4 < tend) ? (tb + 4) : tend;
#pragma unroll
            for (int i = 0; i < 4; ++i) {
                const int t = tb + i;
                if (t < te) step(t);
            }
#pragma unroll
            for (int i = 0; i < 4; ++i) issue_row(tb + RING + i);
            CP_COMMIT();
        }
        if (tend < ss) {
            if (lane >= 16) {                  // publish owned upper 64 states
                float4 v = make_float4(a0, a1, a2, a3);
                *(float4*)&pub[w * 64 + (lane - 16) * 4] = v;
            }
            __syncthreads();
            if (w > 0 && lane < 16) {          // refresh lower 64 from warp w-1
                float4 v = *(const float4*)&pub[(w - 1) * 64 + lane * 4];
                a0 = v.x; a1 = v.y; a2 = v.z; a3 = v.w;
            }
            __syncthreads();
        }
    }

    // ---- publish owned alpha at t = ss ----
    {
        const int olo = (w == 0) ? 0   : bw + 64;
        const int ohi = (w == 3) ? 257 : bw + 128;
        if (s0 + 0 >= olo && s0 + 0 < ohi) alphaAt[s0 + 0] = a0;
        if (s0 + 1 >= olo && s0 + 1 < ohi) alphaAt[s0 + 1] = a1;
        if (s0 + 2 >= olo && s0 + 2 < ohi) alphaAt[s0 + 2] = a2;
        if (s0 + 3 >= olo && s0 + 3 < ohi) alphaAt[s0 + 3] = a3;
    }
    for (int t = ss + tid; t < XMAX; t += NTH) states_sh[t] = 0;
    __syncthreads();

    if (tid == 0) {
        const float v1 = alphaAt[pl - 1];
        const float v2 = alphaAt[pl - 2];
        start_sh = (v1 > v2) ? (pl - 1) : (pl - 2);
        out[b] = fmaxf(v1, v2);                              // score
        out[32 + MASK_ELEMS + b] = (float)(yl + 1);          // ylens + 1
    }
    __syncthreads();

    // ---- backtrace (tid 0, LDS chase through bp bytes) ----
    if (tid == 0) {
        int carry = start_sh;
        states_sh[ss - 1] = (short)carry;
        for (int t = ss - 2; t >= 0; --t) {
            const int s  = carry;
            const int wi = (s >= 128) + (s >= 192) + (s >= 256);
            const int local = s - (wi << 6);
            const uint8_t byte = bp_sm[(t + 1) * NTH + (local & ~3) + wi];
            const int kk = local & 3;
            carry = s - (int)((byte >> (2 * kk)) & 3u);
            states_sh[t] = (short)carry;
        }
    }
    __syncthreads();

    // ---- collapse repeats + exclusive non-blank count (8 t's per thread) ----
    const int t_base = tid * 8;
    int prevTok = 0;
    if (t_base > 0) {
        const int sp = states_sh[t_base - 1];
        prevTok = (sp & 1) ? ys[b * YMAX + ((sp - 1) >> 1)] : blank;
    }
    int lsum = 0;
    {
        int pt = prevTok;
#pragma unroll
        for (int i = 0; i < 8; i++) {
            const int st = states_sh[t_base + i];
            const int tk = (st & 1) ? ys[b * YMAX + ((st - 1) >> 1)] : blank;
            const int col = (tk == pt) ? 0 : tk;
            lsum += (col != blank) ? 1 : 0;
            pt = tk;
        }
    }
    int offs = lsum;
#pragma unroll
    for (int d = 1; d < 32; d <<= 1) {
        const int v = __shfl_up_sync(0xffffffffu, offs, d);
        if (lane >= d) offs += v;
    }
    if (lane == 31) wsum[w] = offs;       // warp total
    offs -= lsum;                          // exclusive within warp
    __syncthreads();
    for (int ww = 0; ww < w; ++ww) offs += wsum[ww];
    {
        int pt = prevTok, run = offs;
#pragma unroll
        for (int i = 0; i < 8; i++) {
            const int t = t_base + i;
            g_csum[b * XMAX + t] = (short)run;
            const int st = states_sh[t];
            const int tk = (st & 1) ? ys[b * YMAX + ((st - 1) >> 1)] : blank;
            const int col = (tk == pt) ? 0 : tk;
            run += (col != blank) ? 1 : 0;
            pt = tk;
        }
    }
    if (tid == 0) g_ssv[b] = ss;
}

// ---------------- Stage 3: trigger_mask streaming store ----------------
__global__ __launch_bounds__(256)
void fanat_mask(float* __restrict__ out)
{
    const int bb   = blockIdx.y;
    const int idx4 = blockIdx.x * 256 + threadIdx.x;        // [0, 33024)
    const int rem  = idx4 * 4;                              // [0, 132096)
    const int j    = rem >> 10;                             // XMAX = 1024
    const int t0   = rem & (XMAX - 1);

    const int ss = g_ssv[bb];
    const short4 cs = *(const short4*)(g_csum + bb * XMAX + t0);
    const int cv[4] = {cs.x, cs.y, cs.z, cs.w};

    float4 v;
    float* vv = &v.x;
#pragma unroll
    for (int u = 0; u < 4; u++) {
        const int t = t0 + u;
        const bool in = (t < ss);
        const int c = cv[u];
        bool r;
        if (j < YMAX) r = in && (c == j);
        else          r = in && (c == YMAX || t == ss - 1);
        vv[u] = r ? 1.0f : 0.0f;
    }
    const size_t e = (size_t)bb * ((YMAX + 1) * XMAX) + rem;
    *(float4*)(out + 32 + e) = v;
}

extern "C" void kernel_launch(void* const* d_in, const int* in_sizes, int n_in,
                              void* d_out, int out_size)
{
    // metadata order: ctc_out(f32), src_mask(bool, unused), src_size(i32),
    //                 ys(i32), ylens(i32), blank(i32 scalar)
    const float* ctc      = (const float*)d_in[0];
    const int*   src_size = (const int*)d_in[2];
    const int*   ys       = (const int*)d_in[3];
    const int*   ylens    = (const int*)d_in[4];
    const int*   blank_p  = (n_in > 5) ? (const int*)d_in[5] : nullptr;

    {   // Stage 1: gather (compact layout)
        const int total = BSZ * XMAX * GROW;
        fanat_gather<<<(total + 255) / 256, 256>>>(ctc, ys, blank_p);
    }

    {   // Stage 2: forward Viterbi + backtrace + csum
        const int smem = XMAX * NTH + 4 * RING * SLICEB;    // 128K + 17K
        cudaFuncSetAttribute(fanat_forward,
                             cudaFuncAttributeMaxDynamicSharedMemorySize, smem);
        fanat_forward<<<BSZ, NTH, smem>>>(src_size, ys, ylens, blank_p, (float*)d_out);
    }

    {   // Stage 3: trigger_mask
        dim3 grid((YMAX + 1) * XMAX / 4 / 256, BSZ);        // (129, 32)
        fanat_mask<<<grid, 256>>>((float*)d_out);
    }
}

// round 14
// speedup vs baseline: 1.3618x; 1.0131x over previous
#include <cuda_runtime.h>
#include <stdint.h>

// Problem constants (from reference setup_inputs)
#define BSZ      32
#define XMAX     1024
#define VOCAB    1000
#define YMAX     128
#define LSTATES  257                   // 2*YMAX + 1
#define LOGZERO  (-1e10f)
#define GROW     132                   // compact gathered row floats: 128 tok + blank + pad
#define ROWB     (GROW * 4)            // 528 bytes
#define SLICEB   272                   // per-warp ring slot: 32*8B + 4B blank, padded
#define RING     32                    // ring depth (rows), 8 groups of 4
#define REF      32                    // refresh period (steps)
#define NTH      128                   // 4 warps

#define MASK_ELEMS ((size_t)BSZ * (YMAX + 1) * XMAX)   // 32*129*1024

// cross-kernel scratch (static device globals: allocation-guard legal)
__device__ __align__(16) float g_gather[(size_t)BSZ * XMAX * GROW];  // ~17 MB
__device__ __align__(16) short g_csum[BSZ * XMAX];
__device__ int   g_ssv[BSZ];

// dynamic smem: [0,128KB) bp bytes | [128KB, +4*RING*SLICEB) per-warp rings
extern __shared__ uint8_t dyn_sm[];

__device__ __forceinline__ uint32_t smem_u32(const void* p) {
    uint32_t a;
    asm("{ .reg .u64 t; cvta.to.shared.u64 t, %1; cvt.u32.u64 %0, t; }"
        : "=r"(a) : "l"(p));
    return a;
}
__device__ __forceinline__ void cp_async8(uint32_t dst, const void* src) {
    asm volatile("cp.async.ca.shared.global [%0], [%1], 8;" :: "r"(dst), "l"(src));
}
__device__ __forceinline__ void cp_async4(uint32_t dst, const void* src) {
    asm volatile("cp.async.ca.shared.global [%0], [%1], 4;" :: "r"(dst), "l"(src));
}
#define CP_COMMIT() asm volatile("cp.async.commit_group;" ::: "memory")
#define CP_WAIT7()  asm volatile("cp.async.wait_group 7;" ::: "memory")

// ---------------- Stage 1: compact time-invariant gather ----------------
// g_gather[b][t][j] = ctc[b][t][ys[b][j]] for j<128 ; [128] = ctc[b][t][blank]
__global__ __launch_bounds__(256)
void fanat_gather(const float* __restrict__ ctc,
                  const int*   __restrict__ ys,
                  const int*   __restrict__ blank_p)
{
    const int idx = blockIdx.x * 256 + threadIdx.x;
    const int total = BSZ * XMAX * GROW;
    if (idx >= total) return;
    const int j  = idx % GROW;
    if (j > 128) return;
    const int bt = idx / GROW;              // b*XMAX + t
    const int b  = bt >> 10;                // XMAX = 1024

    const int blank = blank_p ? blank_p[0] : 0;
    const int tok = (j < 128) ? ys[b * YMAX + j] : blank;
    g_gather[(size_t)bt * GROW + j] = ctc[(size_t)bt * VOCAB + tok];
}

// ---------------- Stage 2: 4-warp-per-batch Viterbi ----------------
__global__ __launch_bounds__(NTH, 1)
void fanat_forward(const int*   __restrict__ src_size,
                   const int*   __restrict__ ys,
                   const int*   __restrict__ ylens,
                   const int*   __restrict__ blank_p,
                   float*       __restrict__ out)
{
    __shared__ float alphaAt[LSTATES];
    __shared__ short states_sh[XMAX];
    __shared__ __align__(16) float pub[4 * 64];
    __shared__ int   wsum[4];
    __shared__ int   start_sh;

    uint8_t* bp_sm = dyn_sm;                                   // [XMAX][128] bytes
    uint8_t* rings = dyn_sm + XMAX * NTH;                      // 4 * RING * SLICEB

    const int b    = blockIdx.x;
    const int tid  = threadIdx.x;
    const int w    = tid >> 5;
    const int lane = tid & 31;

    const int blank = blank_p ? blank_p[0] : 0;
    const int ss = src_size[b];
    const int yl = ylens[b];
    const int pl = 2 * yl + 1;

    const int bw = 64 * w;
    const int s0 = bw + 4 * lane;          // first state this lane computes

    bool oF0 = (s0 + 0) >= pl, oF1 = (s0 + 1) >= pl;
    bool oF2 = (s0 + 2) >= pl, oF3 = (s0 + 3) >= pl;

    // token index for odd states s0+1 / s0+3: 32w+2l / +1 (clamped for pad lanes)
    const int i1 = 32 * w + 2 * lane;
    const int i1c = (i1 < 127) ? i1 : 127;
    const int i3c = (i1 + 1 < 127) ? (i1 + 1) : 127;
    bool same1, same3;
    {
        const int p1 = (i1c > 0) ? (i1c - 1) : 0;
        const int p3 = (i3c > 0) ? (i3c - 1) : 0;
        same1 = (s0 + 1 == 1) ? true
              : (ys[b * YMAX + i1c] == ys[b * YMAX + p1]);
        same3 = (ys[b * YMAX + i3c] == ys[b * YMAX + p3]);
    }

    // ring: lane copies/reads only its own 8B chunk + lane0 copies blank
    const char* row0 = (const char*)(g_gather + (size_t)b * XMAX * GROW);
    const int src_off = ((i1 < 126) ? i1 : 126) * 4;    // 8B-aligned, clamped
    uint8_t* warp_ring = rings + w * RING * SLICEB;
    const uint32_t ring_s = smem_u32(warp_ring);
    const uint32_t my_dst = ring_s + lane * 8;

    auto issue_row = [&](int row) {
        int rp = row; if (rp > XMAX - 1) rp = XMAX - 1;
        const char* src = row0 + (size_t)rp * ROWB;
        const uint32_t dst = ring_s + (row & (RING - 1)) * SLICEB;
        cp_async8(my_dst + (row & (RING - 1)) * SLICEB, src + src_off);
        if (lane == 0) cp_async4(dst + 256, src + 512);  // blank (float 128)
    };

    float a0 = LOGZERO, a1 = LOGZERO, a2 = LOGZERO, a3 = LOGZERO;
    if (w == 0 && lane == 0) a0 = 0.0f;    // alpha0[0] = 0

    const int bp_addr0 = (lane << 2) + w;  // + t*128

    auto step = [&](int t) {
        const int slot = t & (RING - 1);
        const float2 tp = *(const float2*)(warp_ring + slot * SLICEB + lane * 8);
        const float  lb = *(const float*)(warp_ring + slot * SLICEB + 256);
        float h1 = __shfl_up_sync(0xffffffffu, a3, 1);     // alpha[s0-1]
        if (lane == 0) h1 = LOGZERO;

        // k=0 (even: no m2)
        float b0 = fmaxf(a0, h1);  int g0 = (h1 > a0) ? 1 : 0;
        float n0 = (oF0 ? LOGZERO : b0) + lb;
        // k=1 (odd: m2 = alpha[s0-1] unless same)
        float b1 = fmaxf(a1, a0);  int g1 = (a0 > a1) ? 1 : 0;
        float m2a = same1 ? LOGZERO : h1;
        if (m2a > b1) { b1 = m2a; g1 = 2; }
        float n1 = (oF1 ? LOGZERO : b1) + tp.x;
        // k=2 (even)
        float b2 = fmaxf(a2, a1);  int g2 = (a1 > a2) ? 1 : 0;
        float n2 = (oF2 ? LOGZERO : b2) + lb;
        // k=3 (odd: m2 = a1 unless same)
        float b3 = fmaxf(a3, a2);  int g3 = (a2 > a3) ? 1 : 0;
        float m2b = same3 ? LOGZERO : a1;
        if (m2b > b3) { b3 = m2b; g3 = 2; }
        float n3 = (oF3 ? LOGZERO : b3) + tp.y;

        bp_sm[t * NTH + bp_addr0] =
            (uint8_t)(g0 | (g1 << 2) | (g2 << 4) | (g3 << 6));
        a0 = n0; a1 = n1; a2 = n2; a3 = n3;
    };

    auto refresh = [&]() {
        if (lane >= 16) {                  // publish owned upper 64 states
            float4 v = make_float4(a0, a1, a2, a3);
            *(float4*)&pub[w * 64 + (lane - 16) * 4] = v;
        }
        __syncthreads();
        if (w > 0 && lane < 16) {          // refresh lower 64 from warp w-1
            float4 v = *(const float4*)&pub[(w - 1) * 64 + lane * 4];
            a0 = v.x; a1 = v.y; a2 = v.z; a3 = v.w;
        }
        __syncthreads();
    };

    // prologue: 8 groups of 4 rows
#pragma unroll
    for (int g = 0; g < RING / 4; ++g) {
#pragma unroll
        for (int i = 0; i < 4; ++i) issue_row(4 * g + i);
        CP_COMMIT();
    }

    // ---- main loop: full REF-step blocks, unconditional straight-line steps ----
    int t0 = 0;
    while (t0 + REF <= ss) {
        for (int g = 0; g < REF / 4; ++g) {
            const int tb = t0 + 4 * g;
            CP_WAIT7();                    // rows tb..tb+3 resident
            step(tb + 0);
            step(tb + 1);
            step(tb + 2);
            step(tb + 3);
#pragma unroll
            for (int i = 0; i < 4; ++i) issue_row(tb + RING + i);
            CP_COMMIT();
        }
        t0 += REF;
        if (t0 < ss) refresh();
    }
    // ---- tail: < REF steps, guarded; keep issuing to hold 8 pending groups ----
    for (int tb = t0; tb < ss; tb += 4) {
        CP_WAIT7();
#pragma unroll
        for (int i = 0; i < 4; ++i) {
            if (tb + i < ss) step(tb + i);
        }
#pragma unroll
        for (int i = 0; i < 4; ++i) issue_row(tb + RING + i);
        CP_COMMIT();
    }

    // ---- publish owned alpha at t = ss ----
    {
        const int olo = (w == 0) ? 0   : bw + 64;
        const int ohi = (w == 3) ? 257 : bw + 128;
        if (s0 + 0 >= olo && s0 + 0 < ohi) alphaAt[s0 + 0] = a0;
        if (s0 + 1 >= olo && s0 + 1 < ohi) alphaAt[s0 + 1] = a1;
        if (s0 + 2 >= olo && s0 + 2 < ohi) alphaAt[s0 + 2] = a2;
        if (s0 + 3 >= olo && s0 + 3 < ohi) alphaAt[s0 + 3] = a3;
    }
    for (int t = ss + tid; t < XMAX; t += NTH) states_sh[t] = 0;
    __syncthreads();

    if (tid == 0) {
        const float v1 = alphaAt[pl - 1];
        const float v2 = alphaAt[pl - 2];
        start_sh = (v1 > v2) ? (pl - 1) : (pl - 2);
        out[b] = fmaxf(v1, v2);                              // score
        out[32 + MASK_ELEMS + b] = (float)(yl + 1);          // ylens + 1
    }
    __syncthreads();

    // ---- backtrace (tid 0, LDS chase through bp bytes) ----
    if (tid == 0) {
        int carry = start_sh;
        states_sh[ss - 1] = (short)carry;
        for (int t = ss - 2; t >= 0; --t) {
            const int s  = carry;
            const int wi = (s >= 128) + (s >= 192) + (s >= 256);
            const int local = s - (wi << 6);
            const uint8_t byte = bp_sm[(t + 1) * NTH + (local & ~3) + wi];
            const int kk = local & 3;
            carry = s - (int)((byte >> (2 * kk)) & 3u);
            states_sh[t] = (short)carry;
        }
    }
    __syncthreads();

    // ---- collapse repeats + exclusive non-blank count (8 t's per thread) ----
    const int t_base = tid * 8;
    int prevTok = 0;
    if (t_base > 0) {
        const int sp = states_sh[t_base - 1];
        prevTok = (sp & 1) ? ys[b * YMAX + ((sp - 1) >> 1)] : blank;
    }
    int lsum = 0;
    {
        int pt = prevTok;
#pragma unroll
        for (int i = 0; i < 8; i++) {
            const int st = states_sh[t_base + i];
            const int tk = (st & 1) ? ys[b * YMAX + ((st - 1) >> 1)] : blank;
            const int col = (tk == pt) ? 0 : tk;
            lsum += (col != blank) ? 1 : 0;
            pt = tk;
        }
    }
    int offs = lsum;
#pragma unroll
    for (int d = 1; d < 32; d <<= 1) {
        const int v = __shfl_up_sync(0xffffffffu, offs, d);
        if (lane >= d) offs += v;
    }
    if (lane == 31) wsum[w] = offs;       // warp total
    offs -= lsum;                          // exclusive within warp
    __syncthreads();
    for (int ww = 0; ww < w; ++ww) offs += wsum[ww];
    {
        int pt = prevTok, run = offs;
#pragma unroll
        for (int i = 0; i < 8; i++) {
            const int t = t_base + i;
            g_csum[b * XMAX + t] = (short)run;
            const int st = states_sh[t];
            const int tk = (st & 1) ? ys[b * YMAX + ((st - 1) >> 1)] : blank;
            const int col = (tk == pt) ? 0 : tk;
            run += (col != blank) ? 1 : 0;
            pt = tk;
        }
    }
    if (tid == 0) g_ssv[b] = ss;
}

// ---------------- Stage 3: trigger_mask streaming store ----------------
__global__ __launch_bounds__(256)
void fanat_mask(float* __restrict__ out)
{
    const int bb   = blockIdx.y;
    const int idx4 = blockIdx.x * 256 + threadIdx.x;        // [0, 33024)
    const int rem  = idx4 * 4;                              // [0, 132096)
    const int j    = rem >> 10;                             // XMAX = 1024
    const int t0   = rem & (XMAX - 1);

    const int ss = g_ssv[bb];
    const short4 cs = *(const short4*)(g_csum + bb * XMAX + t0);
    const int cv[4] = {cs.x, cs.y, cs.z, cs.w};

    float4 v;
    float* vv = &v.x;
#pragma unroll
    for (int u = 0; u < 4; u++) {
        const int t = t0 + u;
        const bool in = (t < ss);
        const int c = cv[u];
        bool r;
        if (j < YMAX) r = in && (c == j);
        else          r = in && (c == YMAX || t == ss - 1);
        vv[u] = r ? 1.0f : 0.0f;
    }
    const size_t e = (size_t)bb * ((YMAX + 1) * XMAX) + rem;
    *(float4*)(out + 32 + e) = v;
}

extern "C" void kernel_launch(void* const* d_in, const int* in_sizes, int n_in,
                              void* d_out, int out_size)
{
    // metadata order: ctc_out(f32), src_mask(bool, unused), src_size(i32),
    //                 ys(i32), ylens(i32), blank(i32 scalar)
    const float* ctc      = (const float*)d_in[0];
    const int*   src_size = (const int*)d_in[2];
    const int*   ys       = (const int*)d_in[3];
    const int*   ylens    = (const int*)d_in[4];
    const int*   blank_p  = (n_in > 5) ? (const int*)d_in[5] : nullptr;

    {   // Stage 1: gather (compact layout)
        const int total = BSZ * XMAX * GROW;
        fanat_gather<<<(total + 255) / 256, 256>>>(ctc, ys, blank_p);
    }

    {   // Stage 2: forward Viterbi + backtrace + csum
        const int smem = XMAX * NTH + 4 * RING * SLICEB;    // 128K + 34K
        cudaFuncSetAttribute(fanat_forward,
                             cudaFuncAttributeMaxDynamicSharedMemorySize, smem);
        fanat_forward<<<BSZ, NTH, smem>>>(src_size, ys, ylens, blank_p, (float*)d_out);
    }

    {   // Stage 3: trigger_mask
        dim3 grid((YMAX + 1) * XMAX / 4 / 256, BSZ);        // (129, 32)
        fanat_mask<<<grid, 256>>>((float*)d_out);
    }
}